// round 15
// baseline (speedup 1.0000x reference)
#include <cuda_runtime.h>
#include <cuda_fp16.h>
#include <cstdint>

// Problem constants
#define NTOK 49
#define DIM 256
#define H 8
#define DH 32
#define BWIN 2048
#define NW 64
#define QKV_COLS 768
#define MROWS (BWIN * NTOK)  // 100352
#define NBH (BWIN * H)       // 16384

// Scratch (device globals; no allocation allowed)
__device__ __half g_xh[(size_t)MROWS * DIM];
__device__ __half g_attn_outh[(size_t)MROWS * DIM];
__device__ __half g_wh[QKV_COLS * DIM];
__device__ __half g_pwh[DIM * DIM];
// bias in mma-fragment layout: [wh][warp(4)][t(7)][lane(32)] float4; -1e30 at masked coords
__device__ float4 g_biasF[(size_t)NW * H * 4 * 7 * 32];
// per-(window,head) fp16 q/k/v: [bh][49][32]
__device__ __half g_q[(size_t)NBH * NTOK * DH];
__device__ __half g_k[(size_t)NBH * NTOK * DH];
__device__ __half g_v[(size_t)NBH * NTOK * DH];

#define ATT_SCALE 0.17677669529663687f
#define NEG_BIG (-1e30f)

// ---------------------------------------------------------------------------
// Helpers
// ---------------------------------------------------------------------------
__device__ __forceinline__ void cp_async16(uint32_t s, const void* g) {
    asm volatile("cp.async.cg.shared.global [%0], [%1], 16;" :: "r"(s), "l"(g));
}
__device__ __forceinline__ void cp_commit() {
    asm volatile("cp.async.commit_group;");
}
template<int Nw> __device__ __forceinline__ void cp_wait() {
    asm volatile("cp.async.wait_group %0;" :: "n"(Nw));
}
__device__ __forceinline__ void mma_f16(float c[4], const uint32_t a[4], const uint32_t b[2]) {
    asm volatile(
        "mma.sync.aligned.m16n8k16.row.col.f32.f16.f16.f32 "
        "{%0,%1,%2,%3}, {%4,%5,%6,%7}, {%8,%9}, {%0,%1,%2,%3};"
        : "+f"(c[0]), "+f"(c[1]), "+f"(c[2]), "+f"(c[3])
        : "r"(a[0]), "r"(a[1]), "r"(a[2]), "r"(a[3]), "r"(b[0]), "r"(b[1]));
}
__device__ __forceinline__ void ldm_x4(uint32_t& r0, uint32_t& r1, uint32_t& r2, uint32_t& r3,
                                       uint32_t addr) {
    asm volatile("ldmatrix.sync.aligned.m8n8.x4.shared.b16 {%0,%1,%2,%3}, [%4];"
                 : "=r"(r0), "=r"(r1), "=r"(r2), "=r"(r3) : "r"(addr));
}
__device__ __forceinline__ void ldm_x4_t(uint32_t& r0, uint32_t& r1, uint32_t& r2, uint32_t& r3,
                                         uint32_t addr) {
    asm volatile("ldmatrix.sync.aligned.m8n8.x4.trans.shared.b16 {%0,%1,%2,%3}, [%4];"
                 : "=r"(r0), "=r"(r1), "=r"(r2), "=r"(r3) : "r"(addr));
}
__device__ __forceinline__ uint32_t smem_u32(const void* p) {
    uint32_t a;
    asm("{ .reg .u64 t; cvta.to.shared.u64 t, %1; cvt.u32.u64 %0, t; }" : "=r"(a) : "l"(p));
    return a;
}
__device__ __forceinline__ uint32_t pack_h2(float a, float b) {
    __half2 h = __floats2half2_rn(a, b);
    return *reinterpret_cast<uint32_t*>(&h);
}
// 64B-row tile swizzle (attention tiles)
#define SWZ(row, kc) ((uint32_t)(((row) << 6) + ((((kc) ^ (((row) >> 1) & 3))) << 4)))
// 128B-row tile swizzle (GEMM BK=64 tiles)
#define SWZ64(row, kc) ((uint32_t)(((row) << 7) + ((((kc) ^ ((row) & 7))) << 4)))

// ---------------------------------------------------------------------------
// Fused prep: blocks [0,512) build fragment-layout bias (with -1e30 masking);
// remaining blocks convert x / qkv_w / proj_w to fp16.
// ---------------------------------------------------------------------------
#define PREP_BIAS_BLOCKS (NW * H)   // 512

__global__ __launch_bounds__(256) void prep_all(
    const float* __restrict__ mask, const float* __restrict__ rpb,
    const int* __restrict__ ridx, float4* __restrict__ biasF,
    const float4* __restrict__ sa, uint2* __restrict__ da, int na,
    const float4* __restrict__ sb2, uint2* __restrict__ db, int nb,
    const float4* __restrict__ sc, uint2* __restrict__ dc, int nc)
{
    if (blockIdx.x < PREP_BIAS_BLOCKS) {
        const int tid = threadIdx.x;
        if (tid >= 128) return;
        const int wh = blockIdx.x;
        const int w = wh >> 3, h = wh & 7;
        const float* m = mask + (size_t)w * (NTOK * NTOK);
        const int warp = tid >> 5, lane = tid & 31;
        const int r0 = warp * 16 + (lane >> 2);
        const int r1 = r0 + 8;
        float4* o = biasF + ((size_t)wh * 4 + warp) * 7 * 32 + lane;
        #pragma unroll
        for (int t = 0; t < 7; t++) {
            const int c0 = t * 8 + (lane & 3) * 2;
            const int c1 = c0 + 1;
            float4 v = make_float4(NEG_BIG, NEG_BIG, NEG_BIG, NEG_BIG);
            if (r0 < NTOK) {
                if (c0 < NTOK) v.x = m[r0 * NTOK + c0] + rpb[ridx[r0 * NTOK + c0] * H + h];
                if (c1 < NTOK) v.y = m[r0 * NTOK + c1] + rpb[ridx[r0 * NTOK + c1] * H + h];
            }
            if (r1 < NTOK) {
                if (c0 < NTOK) v.z = m[r1 * NTOK + c0] + rpb[ridx[r1 * NTOK + c0] * H + h];
                if (c1 < NTOK) v.w = m[r1 * NTOK + c1] + rpb[ridx[r1 * NTOK + c1] * H + h];
            }
            o[t * 32] = v;
        }
    } else {
        const int total = na + nb + nc;
        const int base = (blockIdx.x - PREP_BIAS_BLOCKS) * blockDim.x + threadIdx.x;
        const int stride = (gridDim.x - PREP_BIAS_BLOCKS) * blockDim.x;
        for (int i = base; i < total; i += stride) {
            const float4* s;
            uint2* d;
            int j = i;
            if (j < na)            { s = sa;  d = da; }
            else if (j < na + nb)  { s = sb2; d = db; j -= na; }
            else                   { s = sc;  d = dc; j -= na + nb; }
            float4 v = s[j];
            d[j] = make_uint2(pack_h2(v.x, v.y), pack_h2(v.z, v.w));
        }
    }
}

// ---------------------------------------------------------------------------
// FP16 tensor-core NT GEMM. Block 128x128, BK=64, 8 warps (2m x 4n).
// 3-stage cp.async pipeline, SINGLE barrier per stage (cutlass-style order:
// wait -> sync -> issue next -> commit -> compute).
// MODE 0: fp32 C + bias. MODE 1: qkv split epilogue.
// ---------------------------------------------------------------------------
#define G_STAGE 32768
#define GEMM_SMEM_BYTES (3 * G_STAGE)   // 98304

template<int MODE>
__global__ __launch_bounds__(256, 2) void gemm_f16(
    const __half* __restrict__ A, const __half* __restrict__ W,
    const float* __restrict__ bias, float* __restrict__ C,
    __half* __restrict__ qh, __half* __restrict__ kh, __half* __restrict__ vh,
    int M, int N, int K)
{
    extern __shared__ __align__(16) char smem[];

    const int tid  = threadIdx.x;
    const int lane = tid & 31;
    const int warp = tid >> 5;
    const int wm = warp >> 2;
    const int wn = warp & 3;
    const int bm = blockIdx.y * 128;
    const int bn = blockIdx.x * 128;

    const uint32_t sb = smem_u32(smem);

    uint32_t dstA[4];
    const __half* srcA[4];
    const __half* srcB[4];
    #pragma unroll
    for (int t = 0; t < 4; t++) {
        const int chunk = tid + t * 256;
        const int row = chunk >> 3, kc = chunk & 7;
        dstA[t] = SWZ64(row, kc);
        srcA[t] = A + (size_t)(bm + row) * K + kc * 8;
        srcB[t] = W + (size_t)(bn + row) * K + kc * 8;
    }

    float acc[4][4][4];
    #pragma unroll
    for (int mt = 0; mt < 4; mt++)
        #pragma unroll
        for (int nt = 0; nt < 4; nt++)
            #pragma unroll
            for (int r = 0; r < 4; r++) acc[mt][nt][r] = 0.f;

    const int NS = K >> 6;

    // prologue: prefetch stages 0 and 1 (two commit groups)
    {
        const uint32_t b0 = sb;
        #pragma unroll
        for (int t = 0; t < 4; t++) cp_async16(b0 + dstA[t], srcA[t]);
        #pragma unroll
        for (int t = 0; t < 4; t++) cp_async16(b0 + 16384 + dstA[t], srcB[t]);
        cp_commit();
        if (NS > 1) {
            const uint32_t b1 = sb + G_STAGE;
            #pragma unroll
            for (int t = 0; t < 4; t++) cp_async16(b1 + dstA[t], srcA[t] + 64);
            #pragma unroll
            for (int t = 0; t < 4; t++) cp_async16(b1 + 16384 + dstA[t], srcB[t] + 64);
        }
        cp_commit();
    }

    const int mat  = lane >> 3;
    const int lrow = lane & 7;

    int buf = 0;
    for (int s = 0; s < NS; s++) {
        // stage-s data resident for this thread (groups <= s complete)
        cp_wait<1>();
        // all warps' stage-s data in smem AND all warps done computing s-1
        __syncthreads();
        // issue stage s+2 into buffer (s+2)%3 == (s-1)%3 (safe after barrier)
        if (s + 2 < NS) {
            const int k0 = (s + 2) << 6;
            int nb = buf + 2; if (nb >= 3) nb -= 3;
            const uint32_t base = sb + nb * G_STAGE;
            #pragma unroll
            for (int t = 0; t < 4; t++) cp_async16(base + dstA[t], srcA[t] + k0);
            #pragma unroll
            for (int t = 0; t < 4; t++) cp_async16(base + 16384 + dstA[t], srcB[t] + k0);
        }
        cp_commit();   // unconditional (empty groups keep accounting)

        const uint32_t sA = sb + buf * G_STAGE;
        const uint32_t sB = sA + 16384;

        #pragma unroll
        for (int ks = 0; ks < 4; ks++) {
            uint32_t af[4][4], bf[4][2];
            #pragma unroll
            for (int mt = 0; mt < 4; mt++) {
                const int arow = wm * 64 + mt * 16 + ((mat & 1) << 3) + lrow;
                const int akc  = (ks << 1) + (mat >> 1);
                ldm_x4(af[mt][0], af[mt][1], af[mt][2], af[mt][3], sA + SWZ64(arow, akc));
            }
            #pragma unroll
            for (int nt2 = 0; nt2 < 2; nt2++) {
                const int brow = wn * 32 + (nt2 << 4) + ((mat >> 1) << 3) + lrow;
                const int bkc  = (ks << 1) + (mat & 1);
                ldm_x4(bf[nt2*2][0], bf[nt2*2][1], bf[nt2*2+1][0], bf[nt2*2+1][1],
                       sB + SWZ64(brow, bkc));
            }
            #pragma unroll
            for (int mt = 0; mt < 4; mt++)
                #pragma unroll
                for (int nt = 0; nt < 4; nt++)
                    mma_f16(acc[mt][nt], af[mt], bf[nt]);
        }
        if (++buf == 3) buf = 0;
    }

    const int group = lane >> 2, tig = lane & 3;
    if (MODE == 0) {
        #pragma unroll
        for (int mt = 0; mt < 4; mt++) {
            const int r = bm + wm * 64 + mt * 16 + group;
            #pragma unroll
            for (int nt = 0; nt < 4; nt++) {
                const int c = bn + wn * 32 + nt * 8 + tig * 2;
                const float bx = bias[c], by = bias[c + 1];
                *reinterpret_cast<float2*>(&C[(size_t)r * N + c]) =
                    make_float2(acc[mt][nt][0] + bx, acc[mt][nt][1] + by);
                *reinterpret_cast<float2*>(&C[(size_t)(r + 8) * N + c]) =
                    make_float2(acc[mt][nt][2] + bx, acc[mt][nt][3] + by);
            }
        }
    } else {
        #pragma unroll
        for (int mt = 0; mt < 4; mt++) {
            const int r = bm + wm * 64 + mt * 16 + group;
            const uint32_t bA = (uint32_t)r / 49u;
            const int tA = r - (int)bA * 49;
            const uint32_t bB = (uint32_t)(r + 8) / 49u;
            const int tB = (r + 8) - (int)bB * 49;
            #pragma unroll
            for (int nt = 0; nt < 4; nt++) {
                const int cc = bn + wn * 32 + nt * 8 + tig * 2;
                const int sidx = cc >> 8;
                const int hh = (cc >> 5) & 7;
                const int dd = cc & 31;
                float v0 = acc[mt][nt][0] + bias[cc];
                float v1 = acc[mt][nt][1] + bias[cc + 1];
                float v2 = acc[mt][nt][2] + bias[cc];
                float v3 = acc[mt][nt][3] + bias[cc + 1];
                const size_t iA = ((size_t)(bA * 8 + hh) * NTOK + tA) * DH + dd;
                const size_t iB = ((size_t)(bB * 8 + hh) * NTOK + tB) * DH + dd;
                if (sidx == 0) {
                    v0 *= ATT_SCALE; v1 *= ATT_SCALE; v2 *= ATT_SCALE; v3 *= ATT_SCALE;
                    *reinterpret_cast<__half2*>(&qh[iA]) = __floats2half2_rn(v0, v1);
                    *reinterpret_cast<__half2*>(&qh[iB]) = __floats2half2_rn(v2, v3);
                } else if (sidx == 1) {
                    *reinterpret_cast<__half2*>(&kh[iA]) = __floats2half2_rn(v0, v1);
                    *reinterpret_cast<__half2*>(&kh[iB]) = __floats2half2_rn(v2, v3);
                } else {
                    *reinterpret_cast<__half2*>(&vh[iA]) = __floats2half2_rn(v0, v1);
                    *reinterpret_cast<__half2*>(&vh[iB]) = __floats2half2_rn(v2, v3);
                }
            }
        }
    }
}

// ---------------------------------------------------------------------------
// Attention: 2 (window,head) pairs per 256-thread CTA. Warps 0-3 -> bh0,
// warps 4-7 -> bh1. Bias (-1e30 masked) from L2 in fragment layout.
// smem: 6 tiles = 24 KB.
// ---------------------------------------------------------------------------
__global__ __launch_bounds__(256) void attn_f16(
    const __half* __restrict__ qh, const __half* __restrict__ kh,
    const __half* __restrict__ vh,
    const float4* __restrict__ biasF,
    __half* __restrict__ out)
{
    __shared__ __align__(16) char smem[6 * 4096];
    const uint32_t sb = smem_u32(smem);

    const int bh0 = blockIdx.x * 2;
    const int tid = threadIdx.x;

    const size_t g0 = (size_t)bh0 * NTOK * DH;
    const size_t g1 = (size_t)(bh0 + 1) * NTOK * DH;
    const __half* gp[6] = { qh + g0, kh + g0, vh + g0,
                            qh + g1, kh + g1, vh + g1 };

    // async fills: 6 tiles x 196 16B chunks
    if (tid < 196) {
        const int row = tid >> 2, kc = tid & 3;
        const uint32_t off = SWZ(row, kc);
        #pragma unroll
        for (int buf = 0; buf < 6; buf++)
            cp_async16(sb + buf * 4096 + off, gp[buf] + row * DH + kc * 8);
    }
    cp_commit();
    // zero pad rows 49..63 of all tiles (6 * 60 = 360 chunks)
    for (int i = tid; i < 360; i += 256) {
        const int buf = i / 60, rem = i - buf * 60;
        const int row = 49 + (rem >> 2), kc = rem & 3;
        *reinterpret_cast<uint4*>(smem + buf * 4096 + SWZ(row, kc)) = make_uint4(0, 0, 0, 0);
    }
    cp_wait<0>();
    __syncthreads();

    const int warp = tid >> 5, lane = tid & 31;
    const int wl = warp & 3;            // warp-local index within its bh
    const int which = warp >> 2;        // 0 -> bh0, 1 -> bh0+1
    const int mybh = bh0 + which;
    const int b = mybh >> 3, h = mybh & 7;
    const uint32_t tQ = sb + which * 3 * 4096;
    const uint32_t tK = tQ + 4096;
    const uint32_t tV = tQ + 8192;

    const int group = lane >> 2, tig = lane & 3;
    const int mat = lane >> 3, lrow = lane & 7;
    const int r0 = wl * 16 + group;

    // ---- QK^T: fp16 ----
    float acc[7][4];
    #pragma unroll
    for (int t = 0; t < 7; t++)
        #pragma unroll
        for (int r = 0; r < 4; r++) acc[t][r] = 0.f;

    #pragma unroll
    for (int kc16 = 0; kc16 < 2; kc16++) {
        const int arow = wl * 16 + ((mat & 1) << 3) + lrow;
        const int akc  = kc16 * 2 + (mat >> 1);
        uint32_t ah[4];
        ldm_x4(ah[0], ah[1], ah[2], ah[3], tQ + SWZ(arow, akc));
        #pragma unroll
        for (int g4 = 0; g4 < 4; g4++) {
            const int brow = g4 * 16 + ((mat >> 1) << 3) + lrow;
            const int bkc  = kc16 * 2 + (mat & 1);
            uint32_t bh2[2][2];
            ldm_x4(bh2[0][0], bh2[0][1], bh2[1][0], bh2[1][1], tK + SWZ(brow, bkc));
            #pragma unroll
            for (int u = 0; u < 2; u++) {
                const int t = g4 * 2 + u;
                if (t < 7) mma_f16(acc[t], ah, bh2[u]);
            }
        }
    }

    // ---- bias add (includes -1e30 masking) + unconditional softmax ----
    const float4* bfp = biasF + ((size_t)(((b & (NW - 1)) << 3) + h) * 4 + wl) * 7 * 32 + lane;
    float mx0 = NEG_BIG, mx1 = NEG_BIG;
    #pragma unroll
    for (int t = 0; t < 7; t++) {
        const float4 bv = __ldg(&bfp[t * 32]);
        acc[t][0] += bv.x;
        acc[t][1] += bv.y;
        acc[t][2] += bv.z;
        acc[t][3] += bv.w;
        mx0 = fmaxf(mx0, fmaxf(acc[t][0], acc[t][1]));
        mx1 = fmaxf(mx1, fmaxf(acc[t][2], acc[t][3]));
    }
    mx0 = fmaxf(mx0, __shfl_xor_sync(0xffffffffu, mx0, 1));
    mx0 = fmaxf(mx0, __shfl_xor_sync(0xffffffffu, mx0, 2));
    mx1 = fmaxf(mx1, __shfl_xor_sync(0xffffffffu, mx1, 1));
    mx1 = fmaxf(mx1, __shfl_xor_sync(0xffffffffu, mx1, 2));

    float s0 = 0.f, s1 = 0.f;
    #pragma unroll
    for (int t = 0; t < 7; t++) {
        acc[t][0] = __expf(acc[t][0] - mx0);
        acc[t][1] = __expf(acc[t][1] - mx0);
        acc[t][2] = __expf(acc[t][2] - mx1);
        acc[t][3] = __expf(acc[t][3] - mx1);
        s0 += acc[t][0] + acc[t][1];
        s1 += acc[t][2] + acc[t][3];
    }
    s0 += __shfl_xor_sync(0xffffffffu, s0, 1);
    s0 += __shfl_xor_sync(0xffffffffu, s0, 2);
    s1 += __shfl_xor_sync(0xffffffffu, s1, 1);
    s1 += __shfl_xor_sync(0xffffffffu, s1, 2);
    const float inv0 = 1.f / s0;
    const float inv1 = 1.f / s1;

    // ---- AV: P in registers as fp16 A-frags; V via ldmatrix.trans ----
    uint32_t pa[4][4];
    #pragma unroll
    for (int kc = 0; kc < 4; kc++) {
        const int t0 = kc * 2, t1 = kc * 2 + 1;
        pa[kc][0] = pack_h2(acc[t0][0] * inv0, acc[t0][1] * inv0);
        pa[kc][1] = pack_h2(acc[t0][2] * inv1, acc[t0][3] * inv1);
        if (t1 < 7) {
            pa[kc][2] = pack_h2(acc[t1][0] * inv0, acc[t1][1] * inv0);
            pa[kc][3] = pack_h2(acc[t1][2] * inv1, acc[t1][3] * inv1);
        } else {
            pa[kc][2] = 0u;
            pa[kc][3] = 0u;
        }
    }

    float av[4][4];
    #pragma unroll
    for (int nt = 0; nt < 4; nt++)
        #pragma unroll
        for (int r = 0; r < 4; r++) av[nt][r] = 0.f;

    #pragma unroll
    for (int kc = 0; kc < 4; kc++) {
        #pragma unroll
        for (int d16 = 0; d16 < 2; d16++) {
            const int vrow = kc * 16 + ((mat & 1) << 3) + lrow;
            const int vkc  = d16 * 2 + (mat >> 1);
            uint32_t bf[2][2];
            ldm_x4_t(bf[0][0], bf[0][1], bf[1][0], bf[1][1], tV + SWZ(vrow, vkc));
            mma_f16(av[d16 * 2],     pa[kc], bf[0]);
            mma_f16(av[d16 * 2 + 1], pa[kc], bf[1]);
        }
    }

    __half* ob = out + (size_t)b * NTOK * DIM + h * DH;
    if (r0 < NTOK) {
        #pragma unroll
        for (int nt = 0; nt < 4; nt++) {
            const int d = nt * 8 + tig * 2;
            *reinterpret_cast<__half2*>(&ob[(size_t)r0 * DIM + d]) =
                __floats2half2_rn(av[nt][0], av[nt][1]);
        }
    }
    if (r0 + 8 < NTOK) {
        #pragma unroll
        for (int nt = 0; nt < 4; nt++) {
            const int d = nt * 8 + tig * 2;
            *reinterpret_cast<__half2*>(&ob[(size_t)(r0 + 8) * DIM + d]) =
                __floats2half2_rn(av[nt][2], av[nt][3]);
        }
    }
}

// ---------------------------------------------------------------------------
// Launch
// ---------------------------------------------------------------------------
extern "C" void kernel_launch(void* const* d_in, const int* in_sizes, int n_in,
                              void* d_out, int out_size) {
    const float* x         = (const float*)d_in[0];
    const float* mask      = (const float*)d_in[1];
    const float* qkv_w     = (const float*)d_in[2];
    const float* qkv_b     = (const float*)d_in[3];
    const float* proj_w    = (const float*)d_in[4];
    const float* proj_b    = (const float*)d_in[5];
    const float* rpb_table = (const float*)d_in[6];
    const int*   rel_index = (const int*)d_in[7];
    float* out = (float*)d_out;

    __half *xh, *aoh, *wh, *pwh, *qh, *kh, *vh;
    float4 *biasF;
    cudaGetSymbolAddress((void**)&xh,  g_xh);
    cudaGetSymbolAddress((void**)&aoh, g_attn_outh);
    cudaGetSymbolAddress((void**)&wh,  g_wh);
    cudaGetSymbolAddress((void**)&pwh, g_pwh);
    cudaGetSymbolAddress((void**)&qh,  g_q);
    cudaGetSymbolAddress((void**)&kh,  g_k);
    cudaGetSymbolAddress((void**)&vh,  g_v);
    cudaGetSymbolAddress((void**)&biasF, g_biasF);

    cudaFuncSetAttribute(gemm_f16<0>,
                         cudaFuncAttributeMaxDynamicSharedMemorySize, GEMM_SMEM_BYTES);
    cudaFuncSetAttribute(gemm_f16<1>,
                         cudaFuncAttributeMaxDynamicSharedMemorySize, GEMM_SMEM_BYTES);

    // 0) fused prep: fragment bias + fp16 conversions (one launch)
    {
        const int na = MROWS * DIM / 4;
        const int nb = QKV_COLS * DIM / 4;
        const int nc = DIM * DIM / 4;
        const int total = na + nb + nc;
        const int cvt_blocks = (total + 255) / 256;
        prep_all<<<PREP_BIAS_BLOCKS + cvt_blocks, 256>>>(
            mask, rpb_table, rel_index, biasF,
            (const float4*)x, (uint2*)xh, na,
            (const float4*)qkv_w, (uint2*)wh, nb,
            (const float4*)proj_w, (uint2*)pwh, nc);
    }
    // 1) QKV projection with fused q/k/v epilogue
    {
        dim3 grid(QKV_COLS / 128, MROWS / 128);
        gemm_f16<1><<<grid, 256, GEMM_SMEM_BYTES>>>(xh, wh, qkv_b, nullptr,
                                                    qh, kh, vh,
                                                    MROWS, QKV_COLS, DIM);
    }
    // 2) attention (2 heads per CTA)
    attn_f16<<<NBH / 2, 256>>>(qh, kh, vh, biasF, aoh);
    // 3) output projection
    {
        dim3 grid(DIM / 128, MROWS / 128);
        gemm_f16<0><<<grid, 256, GEMM_SMEM_BYTES>>>(aoh, pwh, proj_b, out,
                                                    nullptr, nullptr, nullptr,
                                                    MROWS, DIM, DIM);
    }
}